// round 12
// baseline (speedup 1.0000x reference)
#include <cuda_runtime.h>
#include <cuda_fp16.h>
#include <cstdint>

#define B_  64
#define N_  197
#define D_  768
#define H_  12
#define DH_ 64
#define C3  2304          // 3*H*DH
#define MASK_VAL -987654321.0f

#define NP  208           // padded seq len (13 * 16)
#define SQK 72            // Qh/Kh smem row stride (halves)
#define SVT 216           // Vt smem row stride (halves)

// Scratch buffers (device globals: allocation-free contract)
__device__ __half g_qkvh [B_ * N_ * C3];   // fp16 qkv
__device__ __half g_attnh[B_ * N_ * D_];   // fp16 attention output
__device__ __half g_xh   [B_ * N_ * D_];   // fp16 x
__device__ __half g_wqkvh[C3 * D_];        // fp16 W_qkv
__device__ __half g_wouth[D_ * D_];        // fp16 W_out

// ===========================================================================
// Helpers
// ===========================================================================
__device__ __forceinline__ uint32_t smem_u32(const void* p) {
    return (uint32_t)__cvta_generic_to_shared(p);
}

__device__ __forceinline__ void mma_f16(float c[4],
                                        uint32_t a0, uint32_t a1,
                                        uint32_t a2, uint32_t a3,
                                        uint32_t b0, uint32_t b1) {
    asm volatile(
        "mma.sync.aligned.m16n8k16.row.col.f32.f16.f16.f32 "
        "{%0,%1,%2,%3}, {%4,%5,%6,%7}, {%8,%9}, {%0,%1,%2,%3};\n"
        : "+f"(c[0]), "+f"(c[1]), "+f"(c[2]), "+f"(c[3])
        : "r"(a0), "r"(a1), "r"(a2), "r"(a3), "r"(b0), "r"(b1));
}

__device__ __forceinline__ void ldsm_x4(uint32_t& r0, uint32_t& r1,
                                        uint32_t& r2, uint32_t& r3,
                                        uint32_t addr) {
    asm volatile(
        "ldmatrix.sync.aligned.m8n8.x4.shared.b16 {%0,%1,%2,%3}, [%4];"
        : "=r"(r0), "=r"(r1), "=r"(r2), "=r"(r3) : "r"(addr));
}

__device__ __forceinline__ void cp_async16(void* smem_dst, const void* gsrc,
                                           bool pred) {
    uint32_t saddr = smem_u32(smem_dst);
    int sz = pred ? 16 : 0;   // zfill when predicated off
    asm volatile("cp.async.ca.shared.global [%0], [%1], 16, %2;\n"
                 :: "r"(saddr), "l"(gsrc), "r"(sz));
}
__device__ __forceinline__ void cp_commit() {
    asm volatile("cp.async.commit_group;\n");
}
__device__ __forceinline__ void cp_wait0() {
    asm volatile("cp.async.wait_group 0;\n");
}

// ===========================================================================
// fp32 -> fp16 convert
// ===========================================================================
__global__ void __launch_bounds__(256)
f2h_kernel(const float* __restrict__ src, __half* __restrict__ dst) {
    const int i = blockIdx.x * 256 + threadIdx.x;
    float4 v = *(const float4*)(src + (size_t)i * 4);
    *reinterpret_cast<__half2*>(dst + (size_t)i * 4)     =
        __floats2half2_rn(v.x, v.y);
    *reinterpret_cast<__half2*>(dst + (size_t)i * 4 + 2) =
        __floats2half2_rn(v.z, v.w);
}

// ===========================================================================
// fp16 tensor-core GEMM (NT)  -- round-8 configuration (measured 156.9us)
// 128x128 CTA tile, k64 chunks, 8 warps (2m x 4n), warp tile 64x32.
// ===========================================================================
#define GT_K 64
#define TILE_B 16384                     // bytes per operand buffer
#define G16_SMEM (4 * TILE_B)            // 64 KB

__device__ __forceinline__ void g16_load(const __half* __restrict__ P,
                                         int ld, int base, int limit, int k0,
                                         char* sm, int tid) {
    #pragma unroll
    for (int i = 0; i < 4; ++i) {
        const int idx  = tid + i * 256;      // 0..1023
        const int row  = idx >> 3;           // 0..127
        const int c    = idx & 7;            // 16B chunk (8 halves)
        const int phys = c ^ (row & 7);
        const int gr   = base + row;
        const bool ok  = (limit < 0) || (gr < limit);
        const __half* src = P + (size_t)(ok ? gr : 0) * ld + k0 + c * 8;
        cp_async16(sm + row * 128 + phys * 16, src, ok);
    }
}

template <bool OUT_HALF>
__global__ void __launch_bounds__(256)
gemm_h16(const __half* __restrict__ A, const __half* __restrict__ W,
         const float* __restrict__ bias, void* __restrict__ Cv,
         int M, int N, int K) {
    extern __shared__ char smc[];
    const uint32_t sbase = smem_u32(smc);
    const int tid  = threadIdx.x;
    const int lane = tid & 31;
    const int wid  = tid >> 5;
    const int wm   = wid >> 2;           // 0..1
    const int wn   = wid & 3;            // 0..3
    const int gid  = lane >> 2;
    const int qid  = lane & 3;
    const int rowBase = blockIdx.y * 128;
    const int colBase = blockIdx.x * 128;

    float acc[4][4][4];
    #pragma unroll
    for (int i = 0; i < 4; ++i)
        #pragma unroll
        for (int j = 0; j < 4; ++j)
            #pragma unroll
            for (int r = 0; r < 4; ++r) acc[i][j][r] = 0.0f;

    const int T = K / GT_K;   // 12

    g16_load(A, K, rowBase, M,  0, smc,            tid);
    g16_load(W, K, colBase, -1, 0, smc + 2*TILE_B, tid);
    cp_commit();

    // ldmatrix lane address components
    const int a_row = (lane & 15);
    const int a_ch  = (lane >> 4) & 1;
    const int b_rowo = (lane & 7) + ((lane >> 4) & 1) * 8;
    const int b_ch  = (lane >> 3) & 1;

    for (int t = 0; t < T; ++t) {
        cp_wait0();
        __syncthreads();
        if (t + 1 < T) {
            const int nb = (t + 1) & 1;
            g16_load(A, K, rowBase, M,  (t+1)*GT_K, smc + nb*TILE_B,       tid);
            g16_load(W, K, colBase, -1, (t+1)*GT_K, smc + 2*TILE_B + nb*TILE_B, tid);
            cp_commit();
        }

        const uint32_t sA = sbase + (t & 1) * TILE_B;
        const uint32_t sB = sbase + 2*TILE_B + (t & 1) * TILE_B;

        #pragma unroll
        for (int kt = 0; kt < 4; ++kt) {
            uint32_t af[4][4], bf[4][2];
            #pragma unroll
            for (int mt = 0; mt < 4; ++mt) {
                const int row = wm * 64 + mt * 16 + a_row;
                const int ch  = kt * 2 + a_ch;
                ldsm_x4(af[mt][0], af[mt][1], af[mt][2], af[mt][3],
                        sA + row * 128 + (ch ^ (row & 7)) * 16);
            }
            #pragma unroll
            for (int p = 0; p < 2; ++p) {
                const int row = wn * 32 + p * 16 + b_rowo;
                const int ch  = kt * 2 + b_ch;
                ldsm_x4(bf[2*p][0], bf[2*p][1], bf[2*p+1][0], bf[2*p+1][1],
                        sB + row * 128 + (ch ^ (row & 7)) * 16);
            }
            #pragma unroll
            for (int mt = 0; mt < 4; ++mt)
                #pragma unroll
                for (int nt = 0; nt < 4; ++nt)
                    mma_f16(acc[mt][nt], af[mt][0], af[mt][1], af[mt][2],
                            af[mt][3], bf[nt][0], bf[nt][1]);
        }
        __syncthreads();
    }

    // Epilogue
    #pragma unroll
    for (int mt = 0; mt < 4; ++mt) {
        #pragma unroll
        for (int nt = 0; nt < 4; ++nt) {
            const int r0 = rowBase + wm * 64 + mt * 16 + gid;
            const int r1 = r0 + 8;
            const int cc = colBase + wn * 32 + nt * 8 + qid * 2;
            if (OUT_HALF) {
                __half* C = (__half*)Cv;
                if (r0 < M)
                    *reinterpret_cast<__half2*>(C + (size_t)r0 * N + cc) =
                        __floats2half2_rn(acc[mt][nt][0], acc[mt][nt][1]);
                if (r1 < M)
                    *reinterpret_cast<__half2*>(C + (size_t)r1 * N + cc) =
                        __floats2half2_rn(acc[mt][nt][2], acc[mt][nt][3]);
            } else {
                float* C = (float*)Cv;
                float bx = 0.f, by = 0.f;
                if (bias) { bx = bias[cc]; by = bias[cc + 1]; }
                if (r0 < M)
                    *(float2*)(C + (size_t)r0 * N + cc) =
                        make_float2(acc[mt][nt][0] + bx, acc[mt][nt][1] + by);
                if (r1 < M)
                    *(float2*)(C + (size_t)r1 * N + cc) =
                        make_float2(acc[mt][nt][2] + bx, acc[mt][nt][3] + by);
            }
        }
    }
}

// ===========================================================================
// fp16 flash-attention: one CTA per (b, h), 8 warps, 2 CTAs/SM, NO spills.
// Online softmax over 4 column blocks (64,64,64,16 cols). Live S = s[8][4].
// ===========================================================================
#define ATTN_SMEM_BYTES ((2 * NP * SQK + DH_ * SVT) * 2)   // 87552

__global__ void __launch_bounds__(256, 2)
attn_h(const __half* __restrict__ qkvh, const float* __restrict__ scale,
       __half* __restrict__ outp) {
    extern __shared__ __half smh[];
    __half* Qh = smh;
    __half* Kh = smh + NP * SQK;
    __half* Vt = smh + 2 * NP * SQK;

    const int b = blockIdx.y;
    const int h = blockIdx.x;
    const int tid  = threadIdx.x;
    const int w    = tid >> 5;
    const int lane = tid & 31;
    const int gid  = lane >> 2;
    const int qid  = lane & 3;
    const float sc = scale[h];

    const __half* base = qkvh + (size_t)b * N_ * C3 + h * DH_;

    for (int idx = tid; idx < NP * DH_; idx += 256) {
        const int row = idx >> 6;
        const int d   = idx & 63;
        __half q = __float2half(0.f), k = q, v = q;
        if (row < N_) {
            const __half* p = base + (size_t)row * C3 + d;
            q = p[0];
            k = p[D_];
            v = p[2 * D_];
        }
        Qh[row * SQK + d] = __float2half(__half2float(q) * sc);
        Kh[row * SQK + d] = k;
        Vt[d * SVT + row] = v;
    }
    __syncthreads();

    for (int c = w; c < 13; c += 8) {
        const int m0 = c * 16;
        const int r_lo = m0 + gid;
        const int r_hi = r_lo + 8;

        // Q fragments for this chunk (reused across all 4 column blocks)
        uint32_t aq[4][4];
        #pragma unroll
        for (int kt = 0; kt < 4; ++kt) {
            const int kb = kt * 16;
            aq[kt][0] = *(const uint32_t*)&Qh[r_lo * SQK + kb + 2*qid    ];
            aq[kt][1] = *(const uint32_t*)&Qh[r_hi * SQK + kb + 2*qid    ];
            aq[kt][2] = *(const uint32_t*)&Qh[r_lo * SQK + kb + 2*qid + 8];
            aq[kt][3] = *(const uint32_t*)&Qh[r_hi * SQK + kb + 2*qid + 8];
        }

        float o[8][4];
        #pragma unroll
        for (int nt = 0; nt < 8; ++nt)
            #pragma unroll
            for (int i = 0; i < 4; ++i) o[nt][i] = 0.f;

        float m_lo = -3.0e38f, m_hi = -3.0e38f;
        float l_lo = 0.f,      l_hi = 0.f;

        #pragma unroll
        for (int blk = 0; blk < 4; ++blk) {
            const int NTB = (blk == 3) ? 2 : 8;   // valid n-tiles this block

            // ---- S block = Q K^T ----
            float s[8][4];
            #pragma unroll
            for (int nt = 0; nt < 8; ++nt)
                if (nt < NTB) {
                    s[nt][0] = 0.f; s[nt][1] = 0.f;
                    s[nt][2] = 0.f; s[nt][3] = 0.f;
                }
            #pragma unroll
            for (int kt = 0; kt < 4; ++kt) {
                const int kb = kt * 16;
                #pragma unroll
                for (int nt = 0; nt < 8; ++nt) {
                    if (nt >= NTB) continue;
                    const int g = blk * 8 + nt;
                    const __half* kr = &Kh[(g * 8 + gid) * SQK + kb + 2*qid];
                    const uint32_t b0 = *(const uint32_t*)(kr);
                    const uint32_t b1 = *(const uint32_t*)(kr + 8);
                    mma_f16(s[nt], aq[kt][0], aq[kt][1], aq[kt][2], aq[kt][3],
                            b0, b1);
                }
            }

            // ---- mask + block max ----
            float bm_lo = -3.0e38f, bm_hi = -3.0e38f;
            #pragma unroll
            for (int nt = 0; nt < 8; ++nt) {
                if (nt >= NTB) continue;
                const int j0 = (blk * 8 + nt) * 8 + 2 * qid;
                const int j1 = j0 + 1;
                float v0 = s[nt][0], v1 = s[nt][1], v2 = s[nt][2], v3 = s[nt][3];
                v0 = (j0 >= N_) ? -3.0e38f : ((j0 == r_lo) ? MASK_VAL : v0);
                v1 = (j1 >= N_) ? -3.0e38f : ((j1 == r_lo) ? MASK_VAL : v1);
                v2 = (j0 >= N_) ? -3.0e38f : ((j0 == r_hi) ? MASK_VAL : v2);
                v3 = (j1 >= N_) ? -3.0e38f : ((j1 == r_hi) ? MASK_VAL : v3);
                s[nt][0] = v0; s[nt][1] = v1; s[nt][2] = v2; s[nt][3] = v3;
                bm_lo = fmaxf(bm_lo, fmaxf(v0, v1));
                bm_hi = fmaxf(bm_hi, fmaxf(v2, v3));
            }
            bm_lo = fmaxf(bm_lo, __shfl_xor_sync(0xffffffffu, bm_lo, 1));
            bm_lo = fmaxf(bm_lo, __shfl_xor_sync(0xffffffffu, bm_lo, 2));
            bm_hi = fmaxf(bm_hi, __shfl_xor_sync(0xffffffffu, bm_hi, 1));
            bm_hi = fmaxf(bm_hi, __shfl_xor_sync(0xffffffffu, bm_hi, 2));

            // ---- online softmax update ----
            const float mn_lo = fmaxf(m_lo, bm_lo);
            const float mn_hi = fmaxf(m_hi, bm_hi);
            const float sc_lo = __expf(m_lo - mn_lo);
            const float sc_hi = __expf(m_hi - mn_hi);
            m_lo = mn_lo; m_hi = mn_hi;

            float bs_lo = 0.f, bs_hi = 0.f;
            #pragma unroll
            for (int nt = 0; nt < 8; ++nt) {
                if (nt >= NTB) continue;
                float e0 = __expf(s[nt][0] - mn_lo);
                float e1 = __expf(s[nt][1] - mn_lo);
                float e2 = __expf(s[nt][2] - mn_hi);
                float e3 = __expf(s[nt][3] - mn_hi);
                s[nt][0] = e0; s[nt][1] = e1; s[nt][2] = e2; s[nt][3] = e3;
                bs_lo += e0 + e1;
                bs_hi += e2 + e3;
            }
            bs_lo += __shfl_xor_sync(0xffffffffu, bs_lo, 1);
            bs_lo += __shfl_xor_sync(0xffffffffu, bs_lo, 2);
            bs_hi += __shfl_xor_sync(0xffffffffu, bs_hi, 1);
            bs_hi += __shfl_xor_sync(0xffffffffu, bs_hi, 2);
            l_lo = l_lo * sc_lo + bs_lo;
            l_hi = l_hi * sc_hi + bs_hi;

            // rescale running O
            #pragma unroll
            for (int nt = 0; nt < 8; ++nt) {
                o[nt][0] *= sc_lo; o[nt][1] *= sc_lo;
                o[nt][2] *= sc_hi; o[nt][3] *= sc_hi;
            }

            // ---- pack P to half2 in place (C layout == A-frag layout) ----
            #pragma unroll
            for (int nt = 0; nt < 8; ++nt) {
                if (nt >= NTB) continue;
                __half2 plo = __floats2half2_rn(s[nt][0], s[nt][1]);
                __half2 phi = __floats2half2_rn(s[nt][2], s[nt][3]);
                s[nt][0] = __uint_as_float(*(uint32_t*)&plo);
                s[nt][1] = __uint_as_float(*(uint32_t*)&phi);
            }

            // ---- O += P V (this block's columns) ----
            const int KT2 = (blk == 3) ? 1 : 4;
            #pragma unroll
            for (int kt2 = 0; kt2 < 4; ++kt2) {
                if (kt2 >= KT2) continue;
                const uint32_t a0 = __float_as_uint(s[2*kt2    ][0]);
                const uint32_t a1 = __float_as_uint(s[2*kt2    ][1]);
                const uint32_t a2 = __float_as_uint(s[2*kt2 + 1][0]);
                const uint32_t a3 = __float_as_uint(s[2*kt2 + 1][1]);
                const int kb = blk * 64 + kt2 * 16;
                #pragma unroll
                for (int ntv = 0; ntv < 8; ++ntv) {
                    const __half* vr = &Vt[(ntv * 8 + gid) * SVT + kb + 2*qid];
                    const uint32_t b0 = *(const uint32_t*)(vr);
                    const uint32_t b1 = *(const uint32_t*)(vr + 8);
                    mma_f16(o[ntv], a0, a1, a2, a3, b0, b1);
                }
            }
        }

        // ---- normalize + store (fp16) ----
        const float inv_lo = 1.0f / l_lo;
        const float inv_hi = 1.0f / l_hi;
        #pragma unroll
        for (int nt = 0; nt < 8; ++nt) {
            const int cc = h * DH_ + nt * 8 + 2 * qid;
            if (r_lo < N_)
                *reinterpret_cast<__half2*>(
                    outp + ((size_t)b * N_ + r_lo) * D_ + cc) =
                    __floats2half2_rn(o[nt][0] * inv_lo, o[nt][1] * inv_lo);
            if (r_hi < N_)
                *reinterpret_cast<__half2*>(
                    outp + ((size_t)b * N_ + r_hi) * D_ + cc) =
                    __floats2half2_rn(o[nt][2] * inv_hi, o[nt][3] * inv_hi);
        }
    }
}

// ===========================================================================
extern "C" void kernel_launch(void* const* d_in, const int* in_sizes, int n_in,
                              void* d_out, int out_size) {
    const float* x     = (const float*)d_in[0];
    const float* Wqkv  = (const float*)d_in[1];
    const float* scale = (const float*)d_in[2];
    const float* Wout  = (const float*)d_in[3];
    const float* bout  = (const float*)d_in[4];
    float* out = (float*)d_out;

    void *p_qkvh, *p_attnh, *p_xh, *p_wqkvh, *p_wouth;
    cudaGetSymbolAddress(&p_qkvh,  g_qkvh);
    cudaGetSymbolAddress(&p_attnh, g_attnh);
    cudaGetSymbolAddress(&p_xh,    g_xh);
    cudaGetSymbolAddress(&p_wqkvh, g_wqkvh);
    cudaGetSymbolAddress(&p_wouth, g_wouth);
    __half* qkvh  = (__half*)p_qkvh;
    __half* attnh = (__half*)p_attnh;
    __half* xh    = (__half*)p_xh;
    __half* wqkvh = (__half*)p_wqkvh;
    __half* wouth = (__half*)p_wouth;

    cudaFuncSetAttribute(gemm_h16<true>,
                         cudaFuncAttributeMaxDynamicSharedMemorySize, G16_SMEM);
    cudaFuncSetAttribute(gemm_h16<false>,
                         cudaFuncAttributeMaxDynamicSharedMemorySize, G16_SMEM);
    cudaFuncSetAttribute(attn_h,
                         cudaFuncAttributeMaxDynamicSharedMemorySize,
                         ATTN_SMEM_BYTES);

    const int M = B_ * N_;  // 12608

    // 0) fp32 -> fp16 converts
    f2h_kernel<<<(B_ * N_ * D_) / 1024, 256>>>(x, xh);
    f2h_kernel<<<(C3 * D_) / 1024, 256>>>(Wqkv, wqkvh);
    f2h_kernel<<<(D_ * D_) / 1024, 256>>>(Wout, wouth);

    // 1) qkv = x @ W_qkv^T   [M, 2304] fp16
    {
        dim3 grid(C3 / 128, (M + 127) / 128);   // 18 x 99
        gemm_h16<true><<<grid, 256, G16_SMEM>>>(xh, wqkvh, nullptr, qkvh,
                                                M, C3, D_);
    }

    // 2) attention per (b, h) -> attnh [M, 768] fp16
    {
        dim3 grid(H_, B_);
        attn_h<<<grid, 256, ATTN_SMEM_BYTES>>>(qkvh, scale, attnh);
    }

    // 3) out = attn @ W_out^T + b_out   [M, 768] fp32
    {
        dim3 grid(D_ / 128, (M + 127) / 128);   // 6 x 99
        gemm_h16<false><<<grid, 256, G16_SMEM>>>(attnh, wouth, bout, out,
                                                 M, D_, D_);
    }
}

// round 13
// speedup vs baseline: 1.0359x; 1.0359x over previous
#include <cuda_runtime.h>
#include <cuda_fp16.h>
#include <cstdint>

#define B_  64
#define N_  197
#define D_  768
#define H_  12
#define DH_ 64
#define C3  2304          // 3*H*DH
#define MASK_VAL -987654321.0f

#define NP  208           // padded seq len (13 * 16)
#define SQK 72            // Qh/Kh smem row stride (halves) - LDSM conflict-free
#define SVT 216           // Vt smem row stride (halves)    - LDSM conflict-free

// Scratch buffers (device globals: allocation-free contract)
__device__ __half g_qkvh [B_ * N_ * C3];   // fp16 qkv
__device__ __half g_attnh[B_ * N_ * D_];   // fp16 attention output
__device__ __half g_xh   [B_ * N_ * D_];   // fp16 x
__device__ __half g_wqkvh[C3 * D_];        // fp16 W_qkv
__device__ __half g_wouth[D_ * D_];        // fp16 W_out

// ===========================================================================
// Helpers
// ===========================================================================
__device__ __forceinline__ uint32_t smem_u32(const void* p) {
    return (uint32_t)__cvta_generic_to_shared(p);
}

__device__ __forceinline__ void mma_f16(float c[4],
                                        uint32_t a0, uint32_t a1,
                                        uint32_t a2, uint32_t a3,
                                        uint32_t b0, uint32_t b1) {
    asm volatile(
        "mma.sync.aligned.m16n8k16.row.col.f32.f16.f16.f32 "
        "{%0,%1,%2,%3}, {%4,%5,%6,%7}, {%8,%9}, {%0,%1,%2,%3};\n"
        : "+f"(c[0]), "+f"(c[1]), "+f"(c[2]), "+f"(c[3])
        : "r"(a0), "r"(a1), "r"(a2), "r"(a3), "r"(b0), "r"(b1));
}

__device__ __forceinline__ void ldsm_x4(uint32_t& r0, uint32_t& r1,
                                        uint32_t& r2, uint32_t& r3,
                                        uint32_t addr) {
    asm volatile(
        "ldmatrix.sync.aligned.m8n8.x4.shared.b16 {%0,%1,%2,%3}, [%4];"
        : "=r"(r0), "=r"(r1), "=r"(r2), "=r"(r3) : "r"(addr));
}

__device__ __forceinline__ void cp_async16(void* smem_dst, const void* gsrc,
                                           bool pred) {
    uint32_t saddr = smem_u32(smem_dst);
    int sz = pred ? 16 : 0;   // zfill when predicated off
    asm volatile("cp.async.ca.shared.global [%0], [%1], 16, %2;\n"
                 :: "r"(saddr), "l"(gsrc), "r"(sz));
}
__device__ __forceinline__ void cp_commit() {
    asm volatile("cp.async.commit_group;\n");
}
__device__ __forceinline__ void cp_wait0() {
    asm volatile("cp.async.wait_group 0;\n");
}

// ===========================================================================
// fp32 -> fp16 convert, three tensors in one launch (float4 granularity)
// ===========================================================================
__global__ void __launch_bounds__(256)
f2h3_kernel(const float* __restrict__ s0, __half* __restrict__ d0, int n0,
            const float* __restrict__ s1, __half* __restrict__ d1, int n1,
            const float* __restrict__ s2, __half* __restrict__ d2, int n2) {
    int i = blockIdx.x * 256 + threadIdx.x;
    const float* s; __half* d;
    if (i < n0)           { s = s0; d = d0; }
    else if (i < n0 + n1) { i -= n0; s = s1; d = d1; }
    else                  { i -= n0 + n1; if (i >= n2) return; s = s2; d = d2; }
    float4 v = *(const float4*)(s + (size_t)i * 4);
    *reinterpret_cast<__half2*>(d + (size_t)i * 4)     =
        __floats2half2_rn(v.x, v.y);
    *reinterpret_cast<__half2*>(d + (size_t)i * 4 + 2) =
        __floats2half2_rn(v.z, v.w);
}

// ===========================================================================
// fp16 tensor-core GEMM (NT)  -- round-8 configuration (measured 156.9us)
// 128x128 CTA tile, k64 chunks, 8 warps (2m x 4n), warp tile 64x32.
// ===========================================================================
#define GT_K 64
#define TILE_B 16384                     // bytes per operand buffer
#define G16_SMEM (4 * TILE_B)            // 64 KB

__device__ __forceinline__ void g16_load(const __half* __restrict__ P,
                                         int ld, int base, int limit, int k0,
                                         char* sm, int tid) {
    #pragma unroll
    for (int i = 0; i < 4; ++i) {
        const int idx  = tid + i * 256;      // 0..1023
        const int row  = idx >> 3;           // 0..127
        const int c    = idx & 7;            // 16B chunk (8 halves)
        const int phys = c ^ (row & 7);
        const int gr   = base + row;
        const bool ok  = (limit < 0) || (gr < limit);
        const __half* src = P + (size_t)(ok ? gr : 0) * ld + k0 + c * 8;
        cp_async16(sm + row * 128 + phys * 16, src, ok);
    }
}

template <bool OUT_HALF>
__global__ void __launch_bounds__(256)
gemm_h16(const __half* __restrict__ A, const __half* __restrict__ W,
         const float* __restrict__ bias, void* __restrict__ Cv,
         int M, int N, int K) {
    extern __shared__ char smc[];
    const uint32_t sbase = smem_u32(smc);
    const int tid  = threadIdx.x;
    const int lane = tid & 31;
    const int wid  = tid >> 5;
    const int wm   = wid >> 2;           // 0..1
    const int wn   = wid & 3;            // 0..3
    const int gid  = lane >> 2;
    const int qid  = lane & 3;
    const int rowBase = blockIdx.y * 128;
    const int colBase = blockIdx.x * 128;

    float acc[4][4][4];
    #pragma unroll
    for (int i = 0; i < 4; ++i)
        #pragma unroll
        for (int j = 0; j < 4; ++j)
            #pragma unroll
            for (int r = 0; r < 4; ++r) acc[i][j][r] = 0.0f;

    const int T = K / GT_K;   // 12

    g16_load(A, K, rowBase, M,  0, smc,            tid);
    g16_load(W, K, colBase, -1, 0, smc + 2*TILE_B, tid);
    cp_commit();

    // ldmatrix lane address components
    const int a_row = (lane & 15);
    const int a_ch  = (lane >> 4) & 1;
    const int b_rowo = (lane & 7) + ((lane >> 4) & 1) * 8;
    const int b_ch  = (lane >> 3) & 1;

    for (int t = 0; t < T; ++t) {
        cp_wait0();
        __syncthreads();
        if (t + 1 < T) {
            const int nb = (t + 1) & 1;
            g16_load(A, K, rowBase, M,  (t+1)*GT_K, smc + nb*TILE_B,       tid);
            g16_load(W, K, colBase, -1, (t+1)*GT_K, smc + 2*TILE_B + nb*TILE_B, tid);
            cp_commit();
        }

        const uint32_t sA = sbase + (t & 1) * TILE_B;
        const uint32_t sB = sbase + 2*TILE_B + (t & 1) * TILE_B;

        #pragma unroll
        for (int kt = 0; kt < 4; ++kt) {
            uint32_t af[4][4], bf[4][2];
            #pragma unroll
            for (int mt = 0; mt < 4; ++mt) {
                const int row = wm * 64 + mt * 16 + a_row;
                const int ch  = kt * 2 + a_ch;
                ldsm_x4(af[mt][0], af[mt][1], af[mt][2], af[mt][3],
                        sA + row * 128 + (ch ^ (row & 7)) * 16);
            }
            #pragma unroll
            for (int p = 0; p < 2; ++p) {
                const int row = wn * 32 + p * 16 + b_rowo;
                const int ch  = kt * 2 + b_ch;
                ldsm_x4(bf[2*p][0], bf[2*p][1], bf[2*p+1][0], bf[2*p+1][1],
                        sB + row * 128 + (ch ^ (row & 7)) * 16);
            }
            #pragma unroll
            for (int mt = 0; mt < 4; ++mt)
                #pragma unroll
                for (int nt = 0; nt < 4; ++nt)
                    mma_f16(acc[mt][nt], af[mt][0], af[mt][1], af[mt][2],
                            af[mt][3], bf[nt][0], bf[nt][1]);
        }
        __syncthreads();
    }

    // Epilogue
    #pragma unroll
    for (int mt = 0; mt < 4; ++mt) {
        #pragma unroll
        for (int nt = 0; nt < 4; ++nt) {
            const int r0 = rowBase + wm * 64 + mt * 16 + gid;
            const int r1 = r0 + 8;
            const int cc = colBase + wn * 32 + nt * 8 + qid * 2;
            if (OUT_HALF) {
                __half* C = (__half*)Cv;
                if (r0 < M)
                    *reinterpret_cast<__half2*>(C + (size_t)r0 * N + cc) =
                        __floats2half2_rn(acc[mt][nt][0], acc[mt][nt][1]);
                if (r1 < M)
                    *reinterpret_cast<__half2*>(C + (size_t)r1 * N + cc) =
                        __floats2half2_rn(acc[mt][nt][2], acc[mt][nt][3]);
            } else {
                float* C = (float*)Cv;
                float bx = 0.f, by = 0.f;
                if (bias) { bx = bias[cc]; by = bias[cc + 1]; }
                if (r0 < M)
                    *(float2*)(C + (size_t)r0 * N + cc) =
                        make_float2(acc[mt][nt][0] + bx, acc[mt][nt][1] + by);
                if (r1 < M)
                    *(float2*)(C + (size_t)r1 * N + cc) =
                        make_float2(acc[mt][nt][2] + bx, acc[mt][nt][3] + by);
            }
        }
    }
}

// ===========================================================================
// fp16 flash-attention: one CTA per (b, h), 8 warps, 2 CTAs/SM.
// cp.async staging for Q/K; all fragments via ldmatrix.x4 (conflict-free
// strides SQK=72, SVT=216). Online softmax over 4 column blocks.
// ===========================================================================
#define ATTN_SMEM_BYTES ((2 * NP * SQK + DH_ * SVT) * 2)   // 87552

__global__ void __launch_bounds__(256, 2)
attn_h(const __half* __restrict__ qkvh, const float* __restrict__ scale,
       __half* __restrict__ outp) {
    extern __shared__ __half smh[];
    __half* Qh = smh;
    __half* Kh = smh + NP * SQK;
    __half* Vt = smh + 2 * NP * SQK;

    const int b = blockIdx.y;
    const int h = blockIdx.x;
    const int tid  = threadIdx.x;
    const int w    = tid >> 5;
    const int lane = tid & 31;
    const int gid  = lane >> 2;
    const int qid  = lane & 3;
    const float sc = scale[h];

    const __half* base = qkvh + (size_t)b * N_ * C3 + h * DH_;

    // Stage Q and K via cp.async (16B chunks, zfill pad rows)
    for (int i = tid; i < NP * 8; i += 256) {      // 1664 chunks
        const int row = i >> 3;
        const int c   = i & 7;
        const bool ok = row < N_;
        const __half* src = base + (size_t)row * C3 + c * 8;
        cp_async16(Qh + row * SQK + c * 8, src,       ok);
        cp_async16(Kh + row * SQK + c * 8, src + D_,  ok);
    }
    cp_commit();

    // Stage V transposed (scalar; once)
    for (int idx = tid; idx < NP * DH_; idx += 256) {
        const int row = idx >> 6;
        const int d   = idx & 63;
        __half v = __float2half(0.f);
        if (row < N_) v = base[(size_t)row * C3 + 2 * D_ + d];
        Vt[d * SVT + row] = v;
    }
    cp_wait0();
    __syncthreads();

    // ldmatrix lane components (same pattern as gemm)
    const int a_row  = lane & 15;
    const int a_ch   = ((lane >> 4) & 1) * 8;      // halves
    const int b_rowo = (lane & 7) + ((lane >> 4) & 1) * 8;
    const int b_ch   = ((lane >> 3) & 1) * 8;      // halves

    for (int c = w; c < 13; c += 8) {
        const int m0 = c * 16;
        const int r_lo = m0 + gid;
        const int r_hi = r_lo + 8;

        // Q fragments for this chunk via LDSM
        uint32_t aq[4][4];
        #pragma unroll
        for (int kt = 0; kt < 4; ++kt)
            ldsm_x4(aq[kt][0], aq[kt][1], aq[kt][2], aq[kt][3],
                    smem_u32(Qh + (m0 + a_row) * SQK + kt * 16 + a_ch));

        float o[8][4];
        #pragma unroll
        for (int nt = 0; nt < 8; ++nt)
            #pragma unroll
            for (int i = 0; i < 4; ++i) o[nt][i] = 0.f;

        float m_lo = -3.0e38f, m_hi = -3.0e38f;
        float l_lo = 0.f,      l_hi = 0.f;

        #pragma unroll
        for (int blk = 0; blk < 4; ++blk) {
            const int NTB = (blk == 3) ? 2 : 8;    // valid n-tiles
            const int NP4 = (blk == 3) ? 1 : 4;    // LDSM groups (16 rows each)

            // ---- S block = Q K^T ----
            float s[8][4];
            #pragma unroll
            for (int nt = 0; nt < 8; ++nt)
                if (nt < NTB) {
                    s[nt][0] = 0.f; s[nt][1] = 0.f;
                    s[nt][2] = 0.f; s[nt][3] = 0.f;
                }
            #pragma unroll
            for (int kt = 0; kt < 4; ++kt) {
                uint32_t bf[8][2];
                #pragma unroll
                for (int p = 0; p < 4; ++p) {
                    if (p >= NP4) continue;
                    ldsm_x4(bf[2*p][0], bf[2*p][1], bf[2*p+1][0], bf[2*p+1][1],
                            smem_u32(Kh + (blk * 64 + p * 16 + b_rowo) * SQK
                                     + kt * 16 + b_ch));
                }
                #pragma unroll
                for (int nt = 0; nt < 8; ++nt) {
                    if (nt >= NTB) continue;
                    mma_f16(s[nt], aq[kt][0], aq[kt][1], aq[kt][2], aq[kt][3],
                            bf[nt][0], bf[nt][1]);
                }
            }

            // ---- scale + mask + block max ----
            float bm_lo = -3.0e38f, bm_hi = -3.0e38f;
            #pragma unroll
            for (int nt = 0; nt < 8; ++nt) {
                if (nt >= NTB) continue;
                const int j0 = (blk * 8 + nt) * 8 + 2 * qid;
                const int j1 = j0 + 1;
                float v0 = s[nt][0] * sc, v1 = s[nt][1] * sc;
                float v2 = s[nt][2] * sc, v3 = s[nt][3] * sc;
                v0 = (j0 >= N_) ? -3.0e38f : ((j0 == r_lo) ? MASK_VAL : v0);
                v1 = (j1 >= N_) ? -3.0e38f : ((j1 == r_lo) ? MASK_VAL : v1);
                v2 = (j0 >= N_) ? -3.0e38f : ((j0 == r_hi) ? MASK_VAL : v2);
                v3 = (j1 >= N_) ? -3.0e38f : ((j1 == r_hi) ? MASK_VAL : v3);
                s[nt][0] = v0; s[nt][1] = v1; s[nt][2] = v2; s[nt][3] = v3;
                bm_lo = fmaxf(bm_lo, fmaxf(v0, v1));
                bm_hi = fmaxf(bm_hi, fmaxf(v2, v3));
            }
            bm_lo = fmaxf(bm_lo, __shfl_xor_sync(0xffffffffu, bm_lo, 1));
            bm_lo = fmaxf(bm_lo, __shfl_xor_sync(0xffffffffu, bm_lo, 2));
            bm_hi = fmaxf(bm_hi, __shfl_xor_sync(0xffffffffu, bm_hi, 1));
            bm_hi = fmaxf(bm_hi, __shfl_xor_sync(0xffffffffu, bm_hi, 2));

            // ---- online softmax update ----
            const float mn_lo = fmaxf(m_lo, bm_lo);
            const float mn_hi = fmaxf(m_hi, bm_hi);
            const float sc_lo = __expf(m_lo - mn_lo);
            const float sc_hi = __expf(m_hi - mn_hi);
            m_lo = mn_lo; m_hi = mn_hi;

            float bs_lo = 0.f, bs_hi = 0.f;
            #pragma unroll
            for (int nt = 0; nt < 8; ++nt) {
                if (nt >= NTB) continue;
                float e0 = __expf(s[nt][0] - mn_lo);
                float e1 = __expf(s[nt][1] - mn_lo);
                float e2 = __expf(s[nt][2] - mn_hi);
                float e3 = __expf(s[nt][3] - mn_hi);
                s[nt][0] = e0; s[nt][1] = e1; s[nt][2] = e2; s[nt][3] = e3;
                bs_lo += e0 + e1;
                bs_hi += e2 + e3;
            }
            bs_lo += __shfl_xor_sync(0xffffffffu, bs_lo, 1);
            bs_lo += __shfl_xor_sync(0xffffffffu, bs_lo, 2);
            bs_hi += __shfl_xor_sync(0xffffffffu, bs_hi, 1);
            bs_hi += __shfl_xor_sync(0xffffffffu, bs_hi, 2);
            l_lo = l_lo * sc_lo + bs_lo;
            l_hi = l_hi * sc_hi + bs_hi;

            #pragma unroll
            for (int nt = 0; nt < 8; ++nt) {
                o[nt][0] *= sc_lo; o[nt][1] *= sc_lo;
                o[nt][2] *= sc_hi; o[nt][3] *= sc_hi;
            }

            // ---- pack P to half2 in place (C layout == A-frag layout) ----
            #pragma unroll
            for (int nt = 0; nt < 8; ++nt) {
                if (nt >= NTB) continue;
                __half2 plo = __floats2half2_rn(s[nt][0], s[nt][1]);
                __half2 phi = __floats2half2_rn(s[nt][2], s[nt][3]);
                s[nt][0] = __uint_as_float(*(uint32_t*)&plo);
                s[nt][1] = __uint_as_float(*(uint32_t*)&phi);
            }

            // ---- O += P V (V^T fragments via LDSM) ----
            const int KT2 = (blk == 3) ? 1 : 4;
            #pragma unroll
            for (int kt2 = 0; kt2 < 4; ++kt2) {
                if (kt2 >= KT2) continue;
                const uint32_t a0 = __float_as_uint(s[2*kt2    ][0]);
                const uint32_t a1 = __float_as_uint(s[2*kt2    ][1]);
                const uint32_t a2 = __float_as_uint(s[2*kt2 + 1][0]);
                const uint32_t a3 = __float_as_uint(s[2*kt2 + 1][1]);
                const int kb = blk * 64 + kt2 * 16;      // j offset (halves)
                uint32_t vf[8][2];
                #pragma unroll
                for (int p = 0; p < 4; ++p) {
                    ldsm_x4(vf[2*p][0], vf[2*p][1], vf[2*p+1][0], vf[2*p+1][1],
                            smem_u32(Vt + (p * 16 + b_rowo) * SVT + kb + b_ch));
                }
                #pragma unroll
                for (int ntv = 0; ntv < 8; ++ntv)
                    mma_f16(o[ntv], a0, a1, a2, a3, vf[ntv][0], vf[ntv][1]);
            }
        }

        // ---- normalize + store (fp16) ----
        const float inv_lo = 1.0f / l_lo;
        const float inv_hi = 1.0f / l_hi;
        #pragma unroll
        for (int nt = 0; nt < 8; ++nt) {
            const int cc = h * DH_ + nt * 8 + 2 * qid;
            if (r_lo < N_)
                *reinterpret_cast<__half2*>(
                    outp + ((size_t)b * N_ + r_lo) * D_ + cc) =
                    __floats2half2_rn(o[nt][0] * inv_lo, o[nt][1] * inv_lo);
            if (r_hi < N_)
                *reinterpret_cast<__half2*>(
                    outp + ((size_t)b * N_ + r_hi) * D_ + cc) =
                    __floats2half2_rn(o[nt][2] * inv_hi, o[nt][3] * inv_hi);
        }
    }
}

// ===========================================================================
extern "C" void kernel_launch(void* const* d_in, const int* in_sizes, int n_in,
                              void* d_out, int out_size) {
    const float* x     = (const float*)d_in[0];
    const float* Wqkv  = (const float*)d_in[1];
    const float* scale = (const float*)d_in[2];
    const float* Wout  = (const float*)d_in[3];
    const float* bout  = (const float*)d_in[4];
    float* out = (float*)d_out;

    void *p_qkvh, *p_attnh, *p_xh, *p_wqkvh, *p_wouth;
    cudaGetSymbolAddress(&p_qkvh,  g_qkvh);
    cudaGetSymbolAddress(&p_attnh, g_attnh);
    cudaGetSymbolAddress(&p_xh,    g_xh);
    cudaGetSymbolAddress(&p_wqkvh, g_wqkvh);
    cudaGetSymbolAddress(&p_wouth, g_wouth);
    __half* qkvh  = (__half*)p_qkvh;
    __half* attnh = (__half*)p_attnh;
    __half* xh    = (__half*)p_xh;
    __half* wqkvh = (__half*)p_wqkvh;
    __half* wouth = (__half*)p_wouth;

    cudaFuncSetAttribute(gemm_h16<true>,
                         cudaFuncAttributeMaxDynamicSharedMemorySize, G16_SMEM);
    cudaFuncSetAttribute(gemm_h16<false>,
                         cudaFuncAttributeMaxDynamicSharedMemorySize, G16_SMEM);
    cudaFuncSetAttribute(attn_h,
                         cudaFuncAttributeMaxDynamicSharedMemorySize,
                         ATTN_SMEM_BYTES);

    const int M = B_ * N_;  // 12608

    // 0) fp32 -> fp16 converts (one launch)
    {
        const int n0 = (B_ * N_ * D_) / 4;
        const int n1 = (C3 * D_) / 4;
        const int n2 = (D_ * D_) / 4;
        const int total = n0 + n1 + n2;
        f2h3_kernel<<<(total + 255) / 256, 256>>>(x, xh, n0, Wqkv, wqkvh, n1,
                                                  Wout, wouth, n2);
    }

    // 1) qkv = x @ W_qkv^T   [M, 2304] fp16
    {
        dim3 grid(C3 / 128, (M + 127) / 128);   // 18 x 99
        gemm_h16<true><<<grid, 256, G16_SMEM>>>(xh, wqkvh, nullptr, qkvh,
                                                M, C3, D_);
    }

    // 2) attention per (b, h) -> attnh [M, 768] fp16
    {
        dim3 grid(H_, B_);
        attn_h<<<grid, 256, ATTN_SMEM_BYTES>>>(qkvh, scale, attnh);
    }

    // 3) out = attn @ W_out^T + b_out   [M, 768] fp32
    {
        dim3 grid(D_ / 128, (M + 127) / 128);   // 6 x 99
        gemm_h16<false><<<grid, 256, G16_SMEM>>>(attnh, wouth, bout, out,
                                                 M, D_, D_);
    }
}

// round 14
// speedup vs baseline: 1.0941x; 1.0561x over previous
#include <cuda_runtime.h>
#include <cuda_fp16.h>
#include <cstdint>

#define B_  64
#define N_  197
#define D_  768
#define H_  12
#define DH_ 64
#define C3  2304          // 3*H*DH
#define MASK_VAL -987654321.0f

#define NP  208           // padded seq len (13 * 16)
#define SQK 72            // Qh/Kh smem row stride (halves) - LDSM conflict-free
#define SVT 216           // Vt smem row stride (halves)    - LDSM conflict-free

// Scratch buffers (device globals: allocation-free contract)
__device__ __half g_qkvh [B_ * N_ * C3];   // fp16 qkv
__device__ __half g_attnh[B_ * N_ * D_];   // fp16 attention output
__device__ __half g_xh   [B_ * N_ * D_];   // fp16 x
__device__ __half g_wqkvh[C3 * D_];        // fp16 W_qkv
__device__ __half g_wouth[D_ * D_];        // fp16 W_out

// ===========================================================================
// Helpers
// ===========================================================================
__device__ __forceinline__ uint32_t smem_u32(const void* p) {
    return (uint32_t)__cvta_generic_to_shared(p);
}

__device__ __forceinline__ void mma_f16(float c[4],
                                        uint32_t a0, uint32_t a1,
                                        uint32_t a2, uint32_t a3,
                                        uint32_t b0, uint32_t b1) {
    asm volatile(
        "mma.sync.aligned.m16n8k16.row.col.f32.f16.f16.f32 "
        "{%0,%1,%2,%3}, {%4,%5,%6,%7}, {%8,%9}, {%0,%1,%2,%3};\n"
        : "+f"(c[0]), "+f"(c[1]), "+f"(c[2]), "+f"(c[3])
        : "r"(a0), "r"(a1), "r"(a2), "r"(a3), "r"(b0), "r"(b1));
}

__device__ __forceinline__ void ldsm_x4(uint32_t& r0, uint32_t& r1,
                                        uint32_t& r2, uint32_t& r3,
                                        uint32_t addr) {
    asm volatile(
        "ldmatrix.sync.aligned.m8n8.x4.shared.b16 {%0,%1,%2,%3}, [%4];"
        : "=r"(r0), "=r"(r1), "=r"(r2), "=r"(r3) : "r"(addr));
}

// L1-bypassing async copy (global -> smem), 16B, zfill when pred==false
__device__ __forceinline__ void cp_async16_cg(void* smem_dst, const void* gsrc,
                                              bool pred) {
    uint32_t saddr = smem_u32(smem_dst);
    int sz = pred ? 16 : 0;
    asm volatile("cp.async.cg.shared.global [%0], [%1], 16, %2;\n"
                 :: "r"(saddr), "l"(gsrc), "r"(sz));
}
__device__ __forceinline__ void cp_commit() {
    asm volatile("cp.async.commit_group;\n");
}
__device__ __forceinline__ void cp_wait0() {
    asm volatile("cp.async.wait_group 0;\n");
}
__device__ __forceinline__ void cp_wait1() {
    asm volatile("cp.async.wait_group 1;\n");
}

// ===========================================================================
// fp32 -> fp16 convert, three tensors in one launch (float4 granularity)
// ===========================================================================
__global__ void __launch_bounds__(256)
f2h3_kernel(const float* __restrict__ s0, __half* __restrict__ d0, int n0,
            const float* __restrict__ s1, __half* __restrict__ d1, int n1,
            const float* __restrict__ s2, __half* __restrict__ d2, int n2) {
    int i = blockIdx.x * 256 + threadIdx.x;
    const float* s; __half* d;
    if (i < n0)           { s = s0; d = d0; }
    else if (i < n0 + n1) { i -= n0; s = s1; d = d1; }
    else                  { i -= n0 + n1; if (i >= n2) return; s = s2; d = d2; }
    float4 v = *(const float4*)(s + (size_t)i * 4);
    *reinterpret_cast<__half2*>(d + (size_t)i * 4)     =
        __floats2half2_rn(v.x, v.y);
    *reinterpret_cast<__half2*>(d + (size_t)i * 4 + 2) =
        __floats2half2_rn(v.z, v.w);
}

// ===========================================================================
// fp16 tensor-core GEMM (NT): 128x128 CTA tile, k64 chunks, 8 warps (2m x 4n),
// warp tile 64x32. 3-stage cp.async.cg ring, one __syncthreads per chunk.
// ===========================================================================
#define GT_K 64
#define TILE_B 16384                     // bytes per operand buffer
#define ST_B   (2 * TILE_B)              // 32 KB per stage (A + B)
#define G16_SMEM (3 * ST_B)              // 96 KB

__device__ __forceinline__ void g16_load(const __half* __restrict__ A,
                                         const __half* __restrict__ W,
                                         int K, int rowBase, int M, int colBase,
                                         int k0, char* st, int tid) {
    char* smA = st;
    char* smB = st + TILE_B;
    #pragma unroll
    for (int i = 0; i < 4; ++i) {
        const int idx  = tid + i * 256;      // 0..1023
        const int row  = idx >> 3;           // 0..127
        const int c    = idx & 7;            // 16B chunk (8 halves)
        const int phys = c ^ (row & 7);
        const int gr   = rowBase + row;
        const bool ok  = gr < M;
        const __half* srcA = A + (size_t)(ok ? gr : 0) * K + k0 + c * 8;
        cp_async16_cg(smA + row * 128 + phys * 16, srcA, ok);
        const __half* srcB = W + (size_t)(colBase + row) * K + k0 + c * 8;
        cp_async16_cg(smB + row * 128 + phys * 16, srcB, true);
    }
}

template <bool OUT_HALF>
__global__ void __launch_bounds__(256)
gemm_h16(const __half* __restrict__ A, const __half* __restrict__ W,
         const float* __restrict__ bias, void* __restrict__ Cv,
         int M, int N, int K) {
    extern __shared__ char smc[];
    const uint32_t sbase = smem_u32(smc);
    const int tid  = threadIdx.x;
    const int lane = tid & 31;
    const int wid  = tid >> 5;
    const int wm   = wid >> 2;           // 0..1
    const int wn   = wid & 3;            // 0..3
    const int gid  = lane >> 2;
    const int qid  = lane & 3;
    const int rowBase = blockIdx.y * 128;
    const int colBase = blockIdx.x * 128;

    float acc[4][4][4];
    #pragma unroll
    for (int i = 0; i < 4; ++i)
        #pragma unroll
        for (int j = 0; j < 4; ++j)
            #pragma unroll
            for (int r = 0; r < 4; ++r) acc[i][j][r] = 0.0f;

    const int T = K / GT_K;   // 12

    g16_load(A, W, K, rowBase, M, colBase, 0,    smc,        tid);
    cp_commit();
    g16_load(A, W, K, rowBase, M, colBase, GT_K, smc + ST_B, tid);
    cp_commit();

    // ldmatrix lane address components
    const int a_row = (lane & 15);
    const int a_ch  = (lane >> 4) & 1;
    const int b_rowo = (lane & 7) + ((lane >> 4) & 1) * 8;
    const int b_ch  = (lane >> 3) & 1;

    int buf = 0;
    for (int t = 0; t < T; ++t) {
        if (t == T - 1) cp_wait0(); else cp_wait1();
        __syncthreads();

        if (t + 2 < T) {
            const int nb = (t + 2) % 3;
            g16_load(A, W, K, rowBase, M, colBase, (t + 2) * GT_K,
                     smc + nb * ST_B, tid);
            cp_commit();
        }

        const uint32_t sA = sbase + buf * ST_B;
        const uint32_t sB = sA + TILE_B;

        #pragma unroll
        for (int kt = 0; kt < 4; ++kt) {
            uint32_t af[4][4], bf[4][2];
            #pragma unroll
            for (int mt = 0; mt < 4; ++mt) {
                const int row = wm * 64 + mt * 16 + a_row;
                const int ch  = kt * 2 + a_ch;
                ldsm_x4(af[mt][0], af[mt][1], af[mt][2], af[mt][3],
                        sA + row * 128 + (ch ^ (row & 7)) * 16);
            }
            #pragma unroll
            for (int p = 0; p < 2; ++p) {
                const int row = wn * 32 + p * 16 + b_rowo;
                const int ch  = kt * 2 + b_ch;
                ldsm_x4(bf[2*p][0], bf[2*p][1], bf[2*p+1][0], bf[2*p+1][1],
                        sB + row * 128 + (ch ^ (row & 7)) * 16);
            }
            #pragma unroll
            for (int mt = 0; mt < 4; ++mt)
                #pragma unroll
                for (int nt = 0; nt < 4; ++nt)
                    mma_f16(acc[mt][nt], af[mt][0], af[mt][1], af[mt][2],
                            af[mt][3], bf[nt][0], bf[nt][1]);
        }
        buf = (buf + 1) % 3;
    }

    // Epilogue
    #pragma unroll
    for (int mt = 0; mt < 4; ++mt) {
        #pragma unroll
        for (int nt = 0; nt < 4; ++nt) {
            const int r0 = rowBase + wm * 64 + mt * 16 + gid;
            const int r1 = r0 + 8;
            const int cc = colBase + wn * 32 + nt * 8 + qid * 2;
            if (OUT_HALF) {
                __half* C = (__half*)Cv;
                if (r0 < M)
                    *reinterpret_cast<__half2*>(C + (size_t)r0 * N + cc) =
                        __floats2half2_rn(acc[mt][nt][0], acc[mt][nt][1]);
                if (r1 < M)
                    *reinterpret_cast<__half2*>(C + (size_t)r1 * N + cc) =
                        __floats2half2_rn(acc[mt][nt][2], acc[mt][nt][3]);
            } else {
                float* C = (float*)Cv;
                float bx = 0.f, by = 0.f;
                if (bias) { bx = bias[cc]; by = bias[cc + 1]; }
                if (r0 < M)
                    *(float2*)(C + (size_t)r0 * N + cc) =
                        make_float2(acc[mt][nt][0] + bx, acc[mt][nt][1] + by);
                if (r1 < M)
                    *(float2*)(C + (size_t)r1 * N + cc) =
                        make_float2(acc[mt][nt][2] + bx, acc[mt][nt][3] + by);
            }
        }
    }
}

// ===========================================================================
// fp16 flash-attention: one CTA per (b, h), 8 warps, 2 CTAs/SM.
// cp.async.cg staging for Q/K; all fragments via ldmatrix.x4. Online softmax.
// ===========================================================================
#define ATTN_SMEM_BYTES ((2 * NP * SQK + DH_ * SVT) * 2)   // 87552

__global__ void __launch_bounds__(256, 2)
attn_h(const __half* __restrict__ qkvh, const float* __restrict__ scale,
       __half* __restrict__ outp) {
    extern __shared__ __half smh[];
    __half* Qh = smh;
    __half* Kh = smh + NP * SQK;
    __half* Vt = smh + 2 * NP * SQK;

    const int b = blockIdx.y;
    const int h = blockIdx.x;
    const int tid  = threadIdx.x;
    const int w    = tid >> 5;
    const int lane = tid & 31;
    const int gid  = lane >> 2;
    const int qid  = lane & 3;
    const float sc = scale[h];

    const __half* base = qkvh + (size_t)b * N_ * C3 + h * DH_;

    // Stage Q and K via cp.async.cg (16B chunks, zfill pad rows)
    for (int i = tid; i < NP * 8; i += 256) {      // 1664 chunks
        const int row = i >> 3;
        const int c   = i & 7;
        const bool ok = row < N_;
        const __half* src = base + (size_t)row * C3 + c * 8;
        cp_async16_cg(Qh + row * SQK + c * 8, src,       ok);
        cp_async16_cg(Kh + row * SQK + c * 8, src + D_,  ok);
    }
    cp_commit();

    // Stage V transposed (scalar; once)
    for (int idx = tid; idx < NP * DH_; idx += 256) {
        const int row = idx >> 6;
        const int d   = idx & 63;
        __half v = __float2half(0.f);
        if (row < N_) v = base[(size_t)row * C3 + 2 * D_ + d];
        Vt[d * SVT + row] = v;
    }
    cp_wait0();
    __syncthreads();

    // ldmatrix lane components
    const int a_row  = lane & 15;
    const int a_ch   = ((lane >> 4) & 1) * 8;      // halves
    const int b_rowo = (lane & 7) + ((lane >> 4) & 1) * 8;
    const int b_ch   = ((lane >> 3) & 1) * 8;      // halves

    for (int c = w; c < 13; c += 8) {
        const int m0 = c * 16;
        const int r_lo = m0 + gid;
        const int r_hi = r_lo + 8;

        uint32_t aq[4][4];
        #pragma unroll
        for (int kt = 0; kt < 4; ++kt)
            ldsm_x4(aq[kt][0], aq[kt][1], aq[kt][2], aq[kt][3],
                    smem_u32(Qh + (m0 + a_row) * SQK + kt * 16 + a_ch));

        float o[8][4];
        #pragma unroll
        for (int nt = 0; nt < 8; ++nt)
            #pragma unroll
            for (int i = 0; i < 4; ++i) o[nt][i] = 0.f;

        float m_lo = -3.0e38f, m_hi = -3.0e38f;
        float l_lo = 0.f,      l_hi = 0.f;

        #pragma unroll
        for (int blk = 0; blk < 4; ++blk) {
            const int NTB = (blk == 3) ? 2 : 8;    // valid n-tiles
            const int NP4 = (blk == 3) ? 1 : 4;    // LDSM groups (16 rows)

            float s[8][4];
            #pragma unroll
            for (int nt = 0; nt < 8; ++nt)
                if (nt < NTB) {
                    s[nt][0] = 0.f; s[nt][1] = 0.f;
                    s[nt][2] = 0.f; s[nt][3] = 0.f;
                }
            #pragma unroll
            for (int kt = 0; kt < 4; ++kt) {
                uint32_t bf[8][2];
                #pragma unroll
                for (int p = 0; p < 4; ++p) {
                    if (p >= NP4) continue;
                    ldsm_x4(bf[2*p][0], bf[2*p][1], bf[2*p+1][0], bf[2*p+1][1],
                            smem_u32(Kh + (blk * 64 + p * 16 + b_rowo) * SQK
                                     + kt * 16 + b_ch));
                }
                #pragma unroll
                for (int nt = 0; nt < 8; ++nt) {
                    if (nt >= NTB) continue;
                    mma_f16(s[nt], aq[kt][0], aq[kt][1], aq[kt][2], aq[kt][3],
                            bf[nt][0], bf[nt][1]);
                }
            }

            float bm_lo = -3.0e38f, bm_hi = -3.0e38f;
            #pragma unroll
            for (int nt = 0; nt < 8; ++nt) {
                if (nt >= NTB) continue;
                const int j0 = (blk * 8 + nt) * 8 + 2 * qid;
                const int j1 = j0 + 1;
                float v0 = s[nt][0] * sc, v1 = s[nt][1] * sc;
                float v2 = s[nt][2] * sc, v3 = s[nt][3] * sc;
                v0 = (j0 >= N_) ? -3.0e38f : ((j0 == r_lo) ? MASK_VAL : v0);
                v1 = (j1 >= N_) ? -3.0e38f : ((j1 == r_lo) ? MASK_VAL : v1);
                v2 = (j0 >= N_) ? -3.0e38f : ((j0 == r_hi) ? MASK_VAL : v2);
                v3 = (j1 >= N_) ? -3.0e38f : ((j1 == r_hi) ? MASK_VAL : v3);
                s[nt][0] = v0; s[nt][1] = v1; s[nt][2] = v2; s[nt][3] = v3;
                bm_lo = fmaxf(bm_lo, fmaxf(v0, v1));
                bm_hi = fmaxf(bm_hi, fmaxf(v2, v3));
            }
            bm_lo = fmaxf(bm_lo, __shfl_xor_sync(0xffffffffu, bm_lo, 1));
            bm_lo = fmaxf(bm_lo, __shfl_xor_sync(0xffffffffu, bm_lo, 2));
            bm_hi = fmaxf(bm_hi, __shfl_xor_sync(0xffffffffu, bm_hi, 1));
            bm_hi = fmaxf(bm_hi, __shfl_xor_sync(0xffffffffu, bm_hi, 2));

            const float mn_lo = fmaxf(m_lo, bm_lo);
            const float mn_hi = fmaxf(m_hi, bm_hi);
            const float sc_lo = __expf(m_lo - mn_lo);
            const float sc_hi = __expf(m_hi - mn_hi);
            m_lo = mn_lo; m_hi = mn_hi;

            float bs_lo = 0.f, bs_hi = 0.f;
            #pragma unroll
            for (int nt = 0; nt < 8; ++nt) {
                if (nt >= NTB) continue;
                float e0 = __expf(s[nt][0] - mn_lo);
                float e1 = __expf(s[nt][1] - mn_lo);
                float e2 = __expf(s[nt][2] - mn_hi);
                float e3 = __expf(s[nt][3] - mn_hi);
                s[nt][0] = e0; s[nt][1] = e1; s[nt][2] = e2; s[nt][3] = e3;
                bs_lo += e0 + e1;
                bs_hi += e2 + e3;
            }
            bs_lo += __shfl_xor_sync(0xffffffffu, bs_lo, 1);
            bs_lo += __shfl_xor_sync(0xffffffffu, bs_lo, 2);
            bs_hi += __shfl_xor_sync(0xffffffffu, bs_hi, 1);
            bs_hi += __shfl_xor_sync(0xffffffffu, bs_hi, 2);
            l_lo = l_lo * sc_lo + bs_lo;
            l_hi = l_hi * sc_hi + bs_hi;

            #pragma unroll
            for (int nt = 0; nt < 8; ++nt) {
                o[nt][0] *= sc_lo; o[nt][1] *= sc_lo;
                o[nt][2] *= sc_hi; o[nt][3] *= sc_hi;
            }

            #pragma unroll
            for (int nt = 0; nt < 8; ++nt) {
                if (nt >= NTB) continue;
                __half2 plo = __floats2half2_rn(s[nt][0], s[nt][1]);
                __half2 phi = __floats2half2_rn(s[nt][2], s[nt][3]);
                s[nt][0] = __uint_as_float(*(uint32_t*)&plo);
                s[nt][1] = __uint_as_float(*(uint32_t*)&phi);
            }

            const int KT2 = (blk == 3) ? 1 : 4;
            #pragma unroll
            for (int kt2 = 0; kt2 < 4; ++kt2) {
                if (kt2 >= KT2) continue;
                const uint32_t a0 = __float_as_uint(s[2*kt2    ][0]);
                const uint32_t a1 = __float_as_uint(s[2*kt2    ][1]);
                const uint32_t a2 = __float_as_uint(s[2*kt2 + 1][0]);
                const uint32_t a3 = __float_as_uint(s[2*kt2 + 1][1]);
                const int kb = blk * 64 + kt2 * 16;      // j offset (halves)
                uint32_t vf[8][2];
                #pragma unroll
                for (int p = 0; p < 4; ++p) {
                    ldsm_x4(vf[2*p][0], vf[2*p][1], vf[2*p+1][0], vf[2*p+1][1],
                            smem_u32(Vt + (p * 16 + b_rowo) * SVT + kb + b_ch));
                }
                #pragma unroll
                for (int ntv = 0; ntv < 8; ++ntv)
                    mma_f16(o[ntv], a0, a1, a2, a3, vf[ntv][0], vf[ntv][1]);
            }
        }

        const float inv_lo = 1.0f / l_lo;
        const float inv_hi = 1.0f / l_hi;
        #pragma unroll
        for (int nt = 0; nt < 8; ++nt) {
            const int cc = h * DH_ + nt * 8 + 2 * qid;
            if (r_lo < N_)
                *reinterpret_cast<__half2*>(
                    outp + ((size_t)b * N_ + r_lo) * D_ + cc) =
                    __floats2half2_rn(o[nt][0] * inv_lo, o[nt][1] * inv_lo);
            if (r_hi < N_)
                *reinterpret_cast<__half2*>(
                    outp + ((size_t)b * N_ + r_hi) * D_ + cc) =
                    __floats2half2_rn(o[nt][2] * inv_hi, o[nt][3] * inv_hi);
        }
    }
}

// ===========================================================================
extern "C" void kernel_launch(void* const* d_in, const int* in_sizes, int n_in,
                              void* d_out, int out_size) {
    const float* x     = (const float*)d_in[0];
    const float* Wqkv  = (const float*)d_in[1];
    const float* scale = (const float*)d_in[2];
    const float* Wout  = (const float*)d_in[3];
    const float* bout  = (const float*)d_in[4];
    float* out = (float*)d_out;

    void *p_qkvh, *p_attnh, *p_xh, *p_wqkvh, *p_wouth;
    cudaGetSymbolAddress(&p_qkvh,  g_qkvh);
    cudaGetSymbolAddress(&p_attnh, g_attnh);
    cudaGetSymbolAddress(&p_xh,    g_xh);
    cudaGetSymbolAddress(&p_wqkvh, g_wqkvh);
    cudaGetSymbolAddress(&p_wouth, g_wouth);
    __half* qkvh  = (__half*)p_qkvh;
    __half* attnh = (__half*)p_attnh;
    __half* xh    = (__half*)p_xh;
    __half* wqkvh = (__half*)p_wqkvh;
    __half* wouth = (__half*)p_wouth;

    cudaFuncSetAttribute(gemm_h16<true>,
                         cudaFuncAttributeMaxDynamicSharedMemorySize, G16_SMEM);
    cudaFuncSetAttribute(gemm_h16<false>,
                         cudaFuncAttributeMaxDynamicSharedMemorySize, G16_SMEM);
    cudaFuncSetAttribute(attn_h,
                         cudaFuncAttributeMaxDynamicSharedMemorySize,
                         ATTN_SMEM_BYTES);

    const int M = B_ * N_;  // 12608

    // 0) fp32 -> fp16 converts (one launch)
    {
        const int n0 = (B_ * N_ * D_) / 4;
        const int n1 = (C3 * D_) / 4;
        const int n2 = (D_ * D_) / 4;
        const int total = n0 + n1 + n2;
        f2h3_kernel<<<(total + 255) / 256, 256>>>(x, xh, n0, Wqkv, wqkvh, n1,
                                                  Wout, wouth, n2);
    }

    // 1) qkv = x @ W_qkv^T   [M, 2304] fp16
    {
        dim3 grid(C3 / 128, (M + 127) / 128);   // 18 x 99
        gemm_h16<true><<<grid, 256, G16_SMEM>>>(xh, wqkvh, nullptr, qkvh,
                                                M, C3, D_);
    }

    // 2) attention per (b, h) -> attnh [M, 768] fp16
    {
        dim3 grid(H_, B_);
        attn_h<<<grid, 256, ATTN_SMEM_BYTES>>>(qkvh, scale, attnh);
    }

    // 3) out = attn @ W_out^T + b_out   [M, 768] fp32
    {
        dim3 grid(D_ / 128, (M + 127) / 128);   // 6 x 99
        gemm_h16<false><<<grid, 256, G16_SMEM>>>(attnh, wouth, bout, out,
                                                 M, D_, D_);
    }
}